// round 12
// baseline (speedup 1.0000x reference)
#include <cuda_runtime.h>
#include <cuda_fp16.h>
#include <cstdint>

// ============================================================================
// out[4096,16384] = f32( fp8( (x_fp8 @ w_fp8^T) / (xs*ws) + bias ) )
// R12: persistent fused quant+GEMM (296 co-resident CTAs). Quantization of
//      each 64-col k-chunk is produced cooperatively during tile-0's k-loop
//      and gated by global arrival counters, hiding quant's 480 MB of DRAM
//      traffic under the GEMM's idle memory pipe (GEMM DRAM was 4.7%).
//      GEMM math identical to R10/R11 (f16 HMMA on e4m3-grid values).
// ============================================================================

#define TOKENS   4096
#define NOUT     16384
#define KDIM     4096

#define TM       128
#define TN       128
#define TKB      128            // K-chunk bytes per smem row = 64 f16
#define KELEM    64
#define STAGES   3
#define NK_ITERS (KDIM / KELEM) // 64
#define ROWB     (KDIM * 2)

#define NTHREADS 128
#define NCTA     296            // 2 CTAs x 148 SMs co-resident (guaranteed)
#define NTILES   4096           // 32 m x 128 n
#define STAGE_BYTES 16384
#define SMEM_TOTAL  (STAGES * 2 * STAGE_BYTES)   // 96 KB -> 2 CTAs/SM

#define N4X ((TOKENS * KDIM) / 4)
#define N4W ((NOUT   * KDIM) / 4)

// quant units: 1 unit = 8 f32 -> 8 f16 (half of a 64-col row-chunk slice)
#define UNITS_TOTAL ((TOKENS + NOUT) * 8)        // 20480 rows * 8 = 163840
#define UPC  ((UNITS_TOTAL + NCTA - 1) / NCTA)   // 554 units per CTA

__device__ __align__(128) uint8_t g_x16[(size_t)TOKENS * KDIM * 2];   // 32 MB
__device__ __align__(128) uint8_t g_w16[(size_t)NOUT   * KDIM * 2];   // 128 MB
__device__ unsigned g_absmax_bits[2];
__device__ int      g_chunk_cnt[NK_ITERS];       // arrivals per k-chunk

// ---------------------------------------------------------------------------
__device__ __forceinline__ uint32_t smem_to_u32(const void* p) {
    uint32_t a;
    asm("{ .reg .u64 t; cvta.to.shared.u64 t, %1; cvt.u32.u64 %0, t; }" : "=r"(a) : "l"(p));
    return a;
}
__device__ __forceinline__ uint16_t cvt2_e4m3(float lo, float hi) {
    uint16_t r;
    asm("cvt.rn.satfinite.e4m3x2.f32 %0, %1, %2;" : "=h"(r) : "f"(hi), "f"(lo));
    return r;
}
__device__ __forceinline__ uint32_t e4m3x2_to_f16x2(uint16_t p) {
    uint32_t h2;
    asm("{ .reg .b16 t; mov.b16 t, %1; cvt.rn.f16x2.e4m3x2 %0, t; }" : "=r"(h2) : "h"(p));
    return h2;
}
__device__ __forceinline__ float2 dec2_e4m3(uint16_t p) {
    uint32_t h2 = e4m3x2_to_f16x2(p);
    __half2 h = *reinterpret_cast<__half2*>(&h2);
    return __half22float2(h);
}
__device__ __forceinline__ void cp_async16(uint32_t smem_dst, const void* gptr) {
    asm volatile("cp.async.cg.shared.global [%0], [%1], 16;" :: "r"(smem_dst), "l"(gptr));
}
__device__ __forceinline__ void cp_commit() {
    asm volatile("cp.async.commit_group;" ::: "memory");
}
template <int N>
__device__ __forceinline__ void cp_wait() {
    asm volatile("cp.async.wait_group %0;" :: "n"(N) : "memory");
}
__device__ __forceinline__ void mma_f16(float* c, const uint32_t* a, const uint32_t* b) {
    asm volatile(
        "mma.sync.aligned.m16n8k16.row.col.f32.f16.f16.f32 "
        "{%0,%1,%2,%3}, {%4,%5,%6,%7}, {%8,%9}, {%0,%1,%2,%3};"
        : "+f"(c[0]), "+f"(c[1]), "+f"(c[2]), "+f"(c[3])
        : "r"(a[0]), "r"(a[1]), "r"(a[2]), "r"(a[3]), "r"(b[0]), "r"(b[1]));
}
__device__ __forceinline__ void ldsm_x4(uint32_t addr,
                                        uint32_t& r0, uint32_t& r1,
                                        uint32_t& r2, uint32_t& r3) {
    asm volatile("ldmatrix.sync.aligned.m8n8.x4.shared.b16 {%0,%1,%2,%3}, [%4];"
                 : "=r"(r0), "=r"(r1), "=r"(r2), "=r"(r3) : "r"(addr));
}
__device__ __forceinline__ uint32_t swz(uint32_t row, uint32_t col) {
    return row * 128u + (((col >> 4) ^ (row & 7u)) << 4) + (col & 15u);
}

// ---------------------------------------------------------------------------
__global__ void init_kernel() {
    if (threadIdx.x < 2) g_absmax_bits[threadIdx.x] = 0u;
    if (threadIdx.x < NK_ITERS) g_chunk_cnt[threadIdx.x] = 0;
}

#define AX_XBLK 1536
#define AX_WBLK 4608
__global__ void absmax_fused_kernel(const float4* __restrict__ x,
                                    const float4* __restrict__ w) {
    const int bx = blockIdx.x;
    const bool isX = bx < AX_XBLK;
    const float4* __restrict__ p = isX ? x : w;
    const int n4   = isX ? N4X : N4W;
    const int nblk = isX ? AX_XBLK : AX_WBLK;
    const int bid  = isX ? bx : bx - AX_XBLK;
    const int slot = isX ? 0 : 1;
    const int stride = nblk * blockDim.x;

    float m0 = 0.f, m1 = 0.f;
    for (int i = bid * blockDim.x + threadIdx.x; i < n4; i += 2 * stride) {
        float4 v = p[i];
        const int j = i + stride;
        if (j < n4) {
            float4 u = p[j];
            m1 = fmaxf(m1, fmaxf(fmaxf(fabsf(u.x), fabsf(u.y)),
                                 fmaxf(fabsf(u.z), fabsf(u.w))));
        }
        m0 = fmaxf(m0, fmaxf(fmaxf(fabsf(v.x), fabsf(v.y)),
                             fmaxf(fabsf(v.z), fabsf(v.w))));
    }
    float m = fmaxf(m0, m1);
    #pragma unroll
    for (int o = 16; o; o >>= 1) m = fmaxf(m, __shfl_xor_sync(0xffffffffu, m, o));
    __shared__ float sm[32];
    if ((threadIdx.x & 31) == 0) sm[threadIdx.x >> 5] = m;
    __syncthreads();
    if (threadIdx.x < 32) {
        float v = (threadIdx.x < (blockDim.x >> 5)) ? sm[threadIdx.x] : 0.f;
        #pragma unroll
        for (int o = 16; o; o >>= 1) v = fmaxf(v, __shfl_xor_sync(0xffffffffu, v, o));
        if (threadIdx.x == 0) atomicMax(&g_absmax_bits[slot], __float_as_uint(v));
    }
}

// ---------------------------------------------------------------------------
// Persistent fused quant + GEMM. grid = 296, block = 128, 2 CTAs/SM.
// ---------------------------------------------------------------------------
__global__ __launch_bounds__(NTHREADS, 2)
void fused_kernel(const float* __restrict__ x, const float* __restrict__ w,
                  const float* __restrict__ bias, float* __restrict__ out)
{
    extern __shared__ char smem[];
    const uint32_t smem_u32 = smem_to_u32(smem);

    const int tid  = threadIdx.x;
    const int wid  = tid >> 5;
    const int lid  = tid & 31;
    const int lr   = lid >> 2;
    const int lc   = lid & 3;
    const int warpM = wid & 1;
    const int warpN = wid >> 1;
    const int lt   = lid & 7;
    const int tile = lid >> 3;

    // scales (absmax kernel completed before this launch)
    const float ax = __uint_as_float(g_absmax_bits[0]);
    const float aw = __uint_as_float(g_absmax_bits[1]);
    const float sx = 448.f / (ax + 1e-6f);
    const float sw = 448.f / (aw + 1e-6f);
    const float inv = 1.0f / (sx * sw);

    // ---- quant producer: my static share of chunk c ----
    auto produce_chunk = [&](int c) {
        const int ubeg = blockIdx.x * UPC;
        const int uend = (ubeg + UPC < UNITS_TOTAL) ? ubeg + UPC : UNITS_TOTAL;
        for (int u = ubeg + tid; u < uend; u += NTHREADS) {
            const int row = u >> 3, sub = u & 7;
            const bool isX = row < TOKENS;
            const int srow = isX ? row : row - TOKENS;
            const float4* __restrict__ src = isX ? (const float4*)x : (const float4*)w;
            const float s = isX ? sx : sw;
            const size_t f4 = (size_t)srow * (KDIM / 4) + c * 16 + sub * 2;
            float4 a = src[f4];
            float4 b = src[f4 + 1];
            uint4 o;
            o.x = e4m3x2_to_f16x2(cvt2_e4m3(a.x * s, a.y * s));
            o.y = e4m3x2_to_f16x2(cvt2_e4m3(a.z * s, a.w * s));
            o.z = e4m3x2_to_f16x2(cvt2_e4m3(b.x * s, b.y * s));
            o.w = e4m3x2_to_f16x2(cvt2_e4m3(b.z * s, b.w * s));
            uint4* __restrict__ dst = isX ? (uint4*)g_x16 : (uint4*)g_w16;
            dst[(size_t)srow * (KDIM / 8) + c * 8 + sub] = o;
        }
        __syncthreads();
        if (tid == 0) {
            __threadfence();                 // release stores to L2
            atomicAdd(&g_chunk_cnt[c], 1);
        }
    };
    auto await_chunk = [&](int c) {
        if (tid == 0) {
            while (atomicAdd(&g_chunk_cnt[c], 0) < NCTA) { }
            __threadfence();                 // acquire
        }
        __syncthreads();
    };

    auto load_stage = [&](const uint8_t* gA, const uint8_t* gB, int st, int kc) {
        const unsigned kOff = (unsigned)kc * TKB;
        const uint32_t sa = smem_u32 + st * 2 * STAGE_BYTES;
        const uint32_t sb = sa + STAGE_BYTES;
        #pragma unroll
        for (int t = 0; t < 8; t++) {
            unsigned idx = tid + t * NTHREADS;
            unsigned row = idx >> 3, g = (idx & 7) << 4;
            cp_async16(sa + swz(row, g), gA + (size_t)row * ROWB + kOff + g);
        }
        #pragma unroll
        for (int t = 0; t < 8; t++) {
            unsigned idx = tid + t * NTHREADS;
            unsigned row = idx >> 3, g = (idx & 7) << 4;
            cp_async16(sb + swz(row, g), gB + (size_t)row * ROWB + kOff + g);
        }
    };

    const unsigned aRow     = (unsigned)(warpM * 64 + (tile & 1) * 8 + lt);
    const unsigned aColHalf = (unsigned)((tile >> 1) * 16);
    const unsigned bRow     = (unsigned)(warpN * 64 + (tile >> 1) * 8 + lt);
    const unsigned bColHalf = (unsigned)((tile & 1) * 16);

    bool first = true;
    for (int t = blockIdx.x; t < NTILES; t += NCTA) {
        const unsigned mBase = (unsigned)(t & 31) * TM;   // fast dim = m (A reuse)
        const unsigned nBase = (unsigned)(t >> 5) * TN;
        const uint8_t* __restrict__ gA = g_x16 + (size_t)mBase * ROWB;
        const uint8_t* __restrict__ gB = g_w16 + (size_t)nBase * ROWB;

        float acc[4][8][4];
        #pragma unroll
        for (int mi = 0; mi < 4; mi++)
            #pragma unroll
            for (int ni = 0; ni < 8; ni++)
                #pragma unroll
                for (int q = 0; q < 4; q++) acc[mi][ni][q] = 0.f;

        if (first) {
            produce_chunk(0); produce_chunk(1); produce_chunk(2);
            await_chunk(0);
            load_stage(gA, gB, 0, 0); cp_commit();
            await_chunk(1);
            load_stage(gA, gB, 1, 1); cp_commit();
        } else {
            load_stage(gA, gB, 0, 0); cp_commit();
            load_stage(gA, gB, 1, 1); cp_commit();
        }

        for (int kc = 0; kc < NK_ITERS; kc++) {
            if (kc < NK_ITERS - 2) cp_wait<1>(); else cp_wait<0>();
            __syncthreads();

            if (first && kc + 3 < NK_ITERS) produce_chunk(kc + 3);
            if (kc + 2 < NK_ITERS) {
                if (first) await_chunk(kc + 2);
                load_stage(gA, gB, (kc + 2) % STAGES, kc + 2);
                cp_commit();
            }

            const int st = kc % STAGES;
            const uint32_t sa = smem_u32 + st * 2 * STAGE_BYTES;
            const uint32_t sb = sa + STAGE_BYTES;

            #pragma unroll
            for (int ks = 0; ks < 4; ks++) {
                const unsigned cb = (unsigned)ks * 32u;
                uint32_t af[4][4];
                #pragma unroll
                for (int mi = 0; mi < 4; mi++)
                    ldsm_x4(sa + swz(aRow + mi * 16u, cb + aColHalf),
                            af[mi][0], af[mi][1], af[mi][2], af[mi][3]);
                uint32_t bf[8][2];
                #pragma unroll
                for (int p = 0; p < 4; p++)
                    ldsm_x4(sb + swz(bRow + p * 16u, cb + bColHalf),
                            bf[2*p][0], bf[2*p][1], bf[2*p+1][0], bf[2*p+1][1]);
                #pragma unroll
                for (int mi = 0; mi < 4; mi++)
                    #pragma unroll
                    for (int ni = 0; ni < 8; ni++)
                        mma_f16(acc[mi][ni], af[mi], bf[ni]);
            }
        }
        first = false;

        // epilogue: descale + bias -> fp8 round -> decode -> f32 store
        #pragma unroll
        for (int mi = 0; mi < 4; mi++) {
            const unsigned r0 = mBase + warpM * 64 + mi * 16 + lr;
            #pragma unroll
            for (int ni = 0; ni < 8; ni++) {
                const unsigned c = nBase + warpN * 64 + ni * 8 + lc * 2;
                const float2 bv = *(const float2*)(bias + c);
                const float* a = acc[mi][ni];
                uint16_t p0 = cvt2_e4m3(fmaf(a[0], inv, bv.x), fmaf(a[1], inv, bv.y));
                uint16_t p1 = cvt2_e4m3(fmaf(a[2], inv, bv.x), fmaf(a[3], inv, bv.y));
                float2 f0 = dec2_e4m3(p0);
                float2 f1 = dec2_e4m3(p1);
                *(float2*)(out + (size_t)r0       * NOUT + c) = f0;
                *(float2*)(out + (size_t)(r0 + 8) * NOUT + c) = f1;
            }
        }
        __syncthreads();   // smem stages reused by next tile
    }
}

// ---------------------------------------------------------------------------
extern "C" void kernel_launch(void* const* d_in, const int* in_sizes, int n_in,
                              void* d_out, int out_size)
{
    const float* x = (const float*)d_in[0];
    const float* w = (const float*)d_in[1];
    const float* b = (const float*)d_in[2];
    float* out = (float*)d_out;

    init_kernel<<<1, 128>>>();                                           // #1
    absmax_fused_kernel<<<AX_XBLK + AX_WBLK, 256>>>((const float4*)x,
                                                    (const float4*)w);   // #2

    cudaFuncSetAttribute(fused_kernel, cudaFuncAttributeMaxDynamicSharedMemorySize, SMEM_TOTAL);
    fused_kernel<<<NCTA, NTHREADS, SMEM_TOTAL>>>(x, w, b, out);          // #3

    (void)in_sizes; (void)n_in; (void)out_size;
}

// round 13
// speedup vs baseline: 1.1385x; 1.1385x over previous
#include <cuda_runtime.h>
#include <cuda_fp16.h>
#include <cstdint>

// ============================================================================
// out[4096,16384] = f32( fp8( (x_fp8 @ w_fp8^T) / (xs*ws) + bias ) )
// R13: revert to R10 GEMM (best: pinned at f32-acc HMMA pipe ceiling).
//      Prepass L2-reversal: quant_w runs right after absmax and traverses w
//      BACK-TO-FRONT, so it starts on the ~126MB of w that absmax left hot
//      in L2 (fused absmax sweeps front-to-back). quant_x runs last.
// ============================================================================

#define TOKENS   4096
#define NOUT     16384
#define KDIM     4096

#define TM       128
#define TN       128
#define TKB      128            // K-chunk bytes per smem row = 64 f16
#define KELEM    64
#define STAGES   3
#define NK_ITERS (KDIM / KELEM) // 64
#define ROWB     (KDIM * 2)

#define NTHREADS 128
#define STAGE_BYTES 16384
#define SMEM_TOTAL  (STAGES * 2 * STAGE_BYTES)   // 96 KB -> 2 CTAs/SM

#define N4X ((TOKENS * KDIM) / 4)
#define N4W ((NOUT   * KDIM) / 4)

__device__ __align__(128) uint8_t g_x16[(size_t)TOKENS * KDIM * 2];   // 32 MB
__device__ __align__(128) uint8_t g_w16[(size_t)NOUT   * KDIM * 2];   // 128 MB
__device__ unsigned g_absmax_bits[2];

// ---------------------------------------------------------------------------
__device__ __forceinline__ uint32_t smem_to_u32(const void* p) {
    uint32_t a;
    asm("{ .reg .u64 t; cvta.to.shared.u64 t, %1; cvt.u32.u64 %0, t; }" : "=r"(a) : "l"(p));
    return a;
}
__device__ __forceinline__ uint16_t cvt2_e4m3(float lo, float hi) {
    uint16_t r;
    asm("cvt.rn.satfinite.e4m3x2.f32 %0, %1, %2;" : "=h"(r) : "f"(hi), "f"(lo));
    return r;
}
__device__ __forceinline__ uint32_t e4m3x2_to_f16x2(uint16_t p) {
    uint32_t h2;
    asm("{ .reg .b16 t; mov.b16 t, %1; cvt.rn.f16x2.e4m3x2 %0, t; }" : "=r"(h2) : "h"(p));
    return h2;
}
__device__ __forceinline__ float2 dec2_e4m3(uint16_t p) {
    uint32_t h2 = e4m3x2_to_f16x2(p);
    __half2 h = *reinterpret_cast<__half2*>(&h2);
    return __half22float2(h);
}
__device__ __forceinline__ void cp_async16(uint32_t smem_dst, const void* gptr) {
    asm volatile("cp.async.cg.shared.global [%0], [%1], 16;" :: "r"(smem_dst), "l"(gptr));
}
__device__ __forceinline__ void cp_commit() {
    asm volatile("cp.async.commit_group;" ::: "memory");
}
template <int N>
__device__ __forceinline__ void cp_wait() {
    asm volatile("cp.async.wait_group %0;" :: "n"(N) : "memory");
}
__device__ __forceinline__ void mma_f16(float* c, const uint32_t* a, const uint32_t* b) {
    asm volatile(
        "mma.sync.aligned.m16n8k16.row.col.f32.f16.f16.f32 "
        "{%0,%1,%2,%3}, {%4,%5,%6,%7}, {%8,%9}, {%0,%1,%2,%3};"
        : "+f"(c[0]), "+f"(c[1]), "+f"(c[2]), "+f"(c[3])
        : "r"(a[0]), "r"(a[1]), "r"(a[2]), "r"(a[3]), "r"(b[0]), "r"(b[1]));
}
__device__ __forceinline__ void ldsm_x4(uint32_t addr,
                                        uint32_t& r0, uint32_t& r1,
                                        uint32_t& r2, uint32_t& r3) {
    asm volatile("ldmatrix.sync.aligned.m8n8.x4.shared.b16 {%0,%1,%2,%3}, [%4];"
                 : "=r"(r0), "=r"(r1), "=r"(r2), "=r"(r3) : "r"(addr));
}
__device__ __forceinline__ uint32_t swz(uint32_t row, uint32_t col) {
    return row * 128u + (((col >> 4) ^ (row & 7u)) << 4) + (col & 15u);
}

// ---------------------------------------------------------------------------
__global__ void init_kernel() {
    if (threadIdx.x < 2) g_absmax_bits[threadIdx.x] = 0u;
}

// Fused absmax: sweeps x and w front-to-back -> L2 ends holding the TAIL of w.
#define AX_XBLK 1536
#define AX_WBLK 4608
__global__ void absmax_fused_kernel(const float4* __restrict__ x,
                                    const float4* __restrict__ w) {
    const int bx = blockIdx.x;
    const bool isX = bx < AX_XBLK;
    const float4* __restrict__ p = isX ? x : w;
    const int n4   = isX ? N4X : N4W;
    const int nblk = isX ? AX_XBLK : AX_WBLK;
    const int bid  = isX ? bx : bx - AX_XBLK;
    const int slot = isX ? 0 : 1;
    const int stride = nblk * blockDim.x;

    float m0 = 0.f, m1 = 0.f;
    for (int i = bid * blockDim.x + threadIdx.x; i < n4; i += 2 * stride) {
        float4 v = p[i];
        const int j = i + stride;
        if (j < n4) {
            float4 u = p[j];
            m1 = fmaxf(m1, fmaxf(fmaxf(fabsf(u.x), fabsf(u.y)),
                                 fmaxf(fabsf(u.z), fabsf(u.w))));
        }
        m0 = fmaxf(m0, fmaxf(fmaxf(fabsf(v.x), fabsf(v.y)),
                             fmaxf(fabsf(v.z), fabsf(v.w))));
    }
    float m = fmaxf(m0, m1);
    #pragma unroll
    for (int o = 16; o; o >>= 1) m = fmaxf(m, __shfl_xor_sync(0xffffffffu, m, o));
    __shared__ float sm[32];
    if ((threadIdx.x & 31) == 0) sm[threadIdx.x >> 5] = m;
    __syncthreads();
    if (threadIdx.x < 32) {
        float v = (threadIdx.x < (blockDim.x >> 5)) ? sm[threadIdx.x] : 0.f;
        #pragma unroll
        for (int o = 16; o; o >>= 1) v = fmaxf(v, __shfl_xor_sync(0xffffffffu, v, o));
        if (threadIdx.x == 0) atomicMax(&g_absmax_bits[slot], __float_as_uint(v));
    }
}

// quant_w: BACK-TO-FRONT traversal — starts on the w tail that absmax left in L2.
__global__ void quant_w_kernel(const float4* __restrict__ w) {
    uint4* __restrict__ out = (uint4*)g_w16;
    const int n8 = N4W / 2;
    float amax = __uint_as_float(g_absmax_bits[1]);
    float s = 448.f / (amax + 1e-6f);
    for (int i = blockIdx.x * blockDim.x + threadIdx.x; i < n8;
         i += gridDim.x * blockDim.x) {
        const int j = n8 - 1 - i;            // reversed sweep
        float4 a = w[2 * j];
        float4 b = w[2 * j + 1];
        uint4 o;
        o.x = e4m3x2_to_f16x2(cvt2_e4m3(a.x * s, a.y * s));
        o.y = e4m3x2_to_f16x2(cvt2_e4m3(a.z * s, a.w * s));
        o.z = e4m3x2_to_f16x2(cvt2_e4m3(b.x * s, b.y * s));
        o.w = e4m3x2_to_f16x2(cvt2_e4m3(b.z * s, b.w * s));
        out[j] = o;
    }
}

__global__ void quant_x_kernel(const float4* __restrict__ x) {
    uint4* __restrict__ out = (uint4*)g_x16;
    const int n8 = N4X / 2;
    float amax = __uint_as_float(g_absmax_bits[0]);
    float s = 448.f / (amax + 1e-6f);
    for (int i = blockIdx.x * blockDim.x + threadIdx.x; i < n8;
         i += gridDim.x * blockDim.x) {
        float4 a = x[2 * i];
        float4 b = x[2 * i + 1];
        uint4 o;
        o.x = e4m3x2_to_f16x2(cvt2_e4m3(a.x * s, a.y * s));
        o.y = e4m3x2_to_f16x2(cvt2_e4m3(a.z * s, a.w * s));
        o.z = e4m3x2_to_f16x2(cvt2_e4m3(b.x * s, b.y * s));
        o.w = e4m3x2_to_f16x2(cvt2_e4m3(b.z * s, b.w * s));
        out[i] = o;
    }
}

// ---------------------------------------------------------------------------
// fp8-grid f16 HMMA GEMM — IDENTICAL to R10 best (tensor-pipe ceiling).
// CTA 128x128, 4 warps, warp tile 64x64, 3-stage cp.async, occ 2.
// ---------------------------------------------------------------------------
__global__ __launch_bounds__(NTHREADS, 2)
void gemm_kernel(const float* __restrict__ bias, float* __restrict__ out)
{
    extern __shared__ char smem[];
    const uint32_t smem_u32 = smem_to_u32(smem);

    const int tid  = threadIdx.x;
    const int wid  = tid >> 5;
    const int lid  = tid & 31;
    const int lr   = lid >> 2;
    const int lc   = lid & 3;
    const int warpM = wid & 1;
    const int warpN = wid >> 1;
    const int lt   = lid & 7;
    const int tile = lid >> 3;

    const unsigned mBase = blockIdx.x * TM;
    const unsigned nBase = blockIdx.y * TN;

    const uint8_t* __restrict__ gA = g_x16 + (size_t)mBase * ROWB;
    const uint8_t* __restrict__ gB = g_w16 + (size_t)nBase * ROWB;

    auto load_stage = [&](int st, int kc) {
        const unsigned kOff = (unsigned)kc * TKB;
        const uint32_t sa = smem_u32 + st * 2 * STAGE_BYTES;
        const uint32_t sb = sa + STAGE_BYTES;
        #pragma unroll
        for (int t = 0; t < 8; t++) {
            unsigned idx = tid + t * NTHREADS;
            unsigned row = idx >> 3, g = (idx & 7) << 4;
            cp_async16(sa + swz(row, g), gA + (size_t)row * ROWB + kOff + g);
        }
        #pragma unroll
        for (int t = 0; t < 8; t++) {
            unsigned idx = tid + t * NTHREADS;
            unsigned row = idx >> 3, g = (idx & 7) << 4;
            cp_async16(sb + swz(row, g), gB + (size_t)row * ROWB + kOff + g);
        }
    };

    float acc[4][8][4];
    #pragma unroll
    for (int mi = 0; mi < 4; mi++)
        #pragma unroll
        for (int ni = 0; ni < 8; ni++)
            #pragma unroll
            for (int q = 0; q < 4; q++) acc[mi][ni][q] = 0.f;

    const unsigned aRow     = (unsigned)(warpM * 64 + (tile & 1) * 8 + lt);
    const unsigned aColHalf = (unsigned)((tile >> 1) * 16);
    const unsigned bRow     = (unsigned)(warpN * 64 + (tile >> 1) * 8 + lt);
    const unsigned bColHalf = (unsigned)((tile & 1) * 16);

    load_stage(0, 0); cp_commit();
    load_stage(1, 1); cp_commit();

    for (int kc = 0; kc < NK_ITERS; kc++) {
        cp_wait<STAGES - 2>();
        __syncthreads();

        if (kc + STAGES - 1 < NK_ITERS) {
            load_stage((kc + STAGES - 1) % STAGES, kc + STAGES - 1);
            cp_commit();
        }

        const int st = kc % STAGES;
        const uint32_t sa = smem_u32 + st * 2 * STAGE_BYTES;
        const uint32_t sb = sa + STAGE_BYTES;

        #pragma unroll
        for (int ks = 0; ks < 4; ks++) {
            const unsigned cb = (unsigned)ks * 32u;
            uint32_t af[4][4];
            #pragma unroll
            for (int mi = 0; mi < 4; mi++)
                ldsm_x4(sa + swz(aRow + mi * 16u, cb + aColHalf),
                        af[mi][0], af[mi][1], af[mi][2], af[mi][3]);
            uint32_t bf[8][2];
            #pragma unroll
            for (int p = 0; p < 4; p++)
                ldsm_x4(sb + swz(bRow + p * 16u, cb + bColHalf),
                        bf[2*p][0], bf[2*p][1], bf[2*p+1][0], bf[2*p+1][1]);
            #pragma unroll
            for (int mi = 0; mi < 4; mi++)
                #pragma unroll
                for (int ni = 0; ni < 8; ni++)
                    mma_f16(acc[mi][ni], af[mi], bf[ni]);
        }
    }

    const float ax = __uint_as_float(g_absmax_bits[0]);
    const float aw = __uint_as_float(g_absmax_bits[1]);
    const float xs = 448.f / (ax + 1e-6f);
    const float ws = 448.f / (aw + 1e-6f);
    const float inv = 1.0f / (xs * ws);

    #pragma unroll
    for (int mi = 0; mi < 4; mi++) {
        const unsigned r0 = mBase + warpM * 64 + mi * 16 + lr;
        #pragma unroll
        for (int ni = 0; ni < 8; ni++) {
            const unsigned c = nBase + warpN * 64 + ni * 8 + lc * 2;
            const float2 bv = *(const float2*)(bias + c);
            const float* a = acc[mi][ni];
            uint16_t p0 = cvt2_e4m3(fmaf(a[0], inv, bv.x), fmaf(a[1], inv, bv.y));
            uint16_t p1 = cvt2_e4m3(fmaf(a[2], inv, bv.x), fmaf(a[3], inv, bv.y));
            float2 f0 = dec2_e4m3(p0);
            float2 f1 = dec2_e4m3(p1);
            *(float2*)(out + (size_t)r0       * NOUT + c) = f0;
            *(float2*)(out + (size_t)(r0 + 8) * NOUT + c) = f1;
        }
    }
}

// ---------------------------------------------------------------------------
extern "C" void kernel_launch(void* const* d_in, const int* in_sizes, int n_in,
                              void* d_out, int out_size)
{
    const float* x = (const float*)d_in[0];
    const float* w = (const float*)d_in[1];
    const float* b = (const float*)d_in[2];
    float* out = (float*)d_out;

    init_kernel<<<1, 32>>>();                                            // #1
    absmax_fused_kernel<<<AX_XBLK + AX_WBLK, 256>>>((const float4*)x,
                                                    (const float4*)w);   // #2
    quant_w_kernel<<<6144, 256>>>((const float4*)w);   // #3 reversed: w tail L2-hot
    quant_x_kernel<<<2048, 256>>>((const float4*)x);   // #4

    cudaFuncSetAttribute(gemm_kernel, cudaFuncAttributeMaxDynamicSharedMemorySize, SMEM_TOTAL);
    dim3 grid(TOKENS / TM, NOUT / TN);   // (32, 128)
    gemm_kernel<<<grid, NTHREADS, SMEM_TOTAL>>>(b, out);                 // #5

    (void)in_sizes; (void)n_in; (void)out_size;
}